// round 15
// baseline (speedup 1.0000x reference)
#include <cuda_runtime.h>
#include <cuda_fp16.h>
#include <math.h>
#include <stdint.h>

// x: (100, 512, 16, 16) fp32 ; W: (512,512) (outC,inC) ; b: (512,) ; out: (75,5)
#define NSAMP 100
#define C 512
#define P 256
#define ELEMS (C*P)
#define WAY 5
#define SHOT 5
#define NQ 75
#define NCHUNK 4
#define CPERCHUNK 128

__device__ __half g_xh[NSAMP * ELEMS];         // x^T fp16 [b][f][c], 26 MB
__device__ __half g_Wh[C * C];                 // W fp16 [o][c]
__device__ __half g_logits[NSAMP * ELEMS];     // [b][f][c] fp16: exp(logit+bias), 26 MB
__device__ float  g_sum[NSAMP];
__device__ float  g_protoAcc[WAY * C];
__device__ float  g_part[NQ * NCHUNK * P * 8];
__device__ float  g_pad_sink[32];

// ===========================================================================
__device__ __forceinline__ uint32_t smem_u32(const void* p) {
    uint32_t a;
    asm("{ .reg .u64 t; cvta.to.shared.u64 t, %1; cvt.u32.u64 %0, t; }"
        : "=r"(a) : "l"(p));
    return a;
}
__device__ __forceinline__ void ldsm4(uint32_t (&r)[4], uint32_t addr) {
    asm volatile("ldmatrix.sync.aligned.m8n8.x4.shared.b16 {%0,%1,%2,%3}, [%4];"
                 : "=r"(r[0]), "=r"(r[1]), "=r"(r[2]), "=r"(r[3]) : "r"(addr));
}
__device__ __forceinline__ void mma16816(float (&d)[4], const uint32_t (&a)[4],
                                         uint32_t b0, uint32_t b1) {
    asm volatile(
        "mma.sync.aligned.m16n8k16.row.col.f32.f16.f16.f32 "
        "{%0,%1,%2,%3},{%4,%5,%6,%7},{%8,%9},{%0,%1,%2,%3};"
        : "+f"(d[0]), "+f"(d[1]), "+f"(d[2]), "+f"(d[3])
        : "r"(a[0]), "r"(a[1]), "r"(a[2]), "r"(a[3]), "r"(b0), "r"(b1));
}
__device__ __forceinline__ uint32_t pkh(float a, float b) {
    __half2 h = __floats2half2_rn(a, b);
    return *(uint32_t*)&h;
}
// 16B-chunk XOR swizzle inside a 64B row (4 chunks)
__device__ __forceinline__ int swz(int row, int ch) {
    return row * 64 + ((ch ^ ((row >> 1) & 3)) << 4);
}
__device__ __forceinline__ void cp16(uint32_t dst, const void* src) {
    asm volatile("cp.async.cg.shared.global [%0], [%1], 16;"
                 :: "r"(dst), "l"(src));
}
#define CP_COMMIT() asm volatile("cp.async.commit_group;" ::: "memory")
#define CP_WAIT2()  asm volatile("cp.async.wait_group 2;" ::: "memory")

// ===========================================================================
// launch 1: zero accumulators (also serves as capture-slot pad)
// ===========================================================================
__global__ void zero_kernel()
{
    for (int i = threadIdx.x; i < NSAMP + WAY * C; i += 256) {
        if (i < NSAMP) g_sum[i] = 0.f;
        else g_protoAcc[i - NSAMP] = 0.f;
    }
}
// launch 2: trivial pad so gemm_mma is launch 4 (ncu capture slot)
__global__ void pad_kernel()
{
    if (threadIdx.x < 32) g_pad_sink[threadIdx.x] = (float)threadIdx.x;
}

// ===========================================================================
// launch 3: convert. b<100: xT fp16 [b][f][c]; b==100: W fp16.
// grid (4, 101), 256 threads.
// ===========================================================================
__global__ __launch_bounds__(256) void conv_kernel(
    const float* __restrict__ x, const float* __restrict__ W)
{
    const int b = blockIdx.y;
    const int f = threadIdx.x;
    if (b < NSAMP) {
        const int c0 = blockIdx.x * 128;
        const float* xb = x + (size_t)b * ELEMS + f;
        __half* dst = g_xh + (size_t)b * ELEMS + (size_t)f * C + c0;
        #pragma unroll
        for (int k = 0; k < 16; k++) {
            const float* sp = xb + (size_t)(c0 + k * 8) * P;
            uint4 u;
            u.x = pkh(sp[0], sp[P]);
            u.y = pkh(sp[2 * P], sp[3 * P]);
            u.z = pkh(sp[4 * P], sp[5 * P]);
            u.w = pkh(sp[6 * P], sp[7 * P]);
            *(uint4*)(dst + k * 8) = u;
        }
    } else {
        const int start = blockIdx.x * 65536;
        #pragma unroll 4
        for (int t = 0; t < 64; t++) {
            const int i4 = start + (t * 256 + threadIdx.x) * 4;
            const float4 v = *(const float4*)(W + i4);
            *(uint2*)(g_Wh + i4) = make_uint2(pkh(v.x, v.y), pkh(v.z, v.w));
        }
    }
}

// ===========================================================================
// launch 4 (ncu capture slot): fp16 mma.sync GEMM, cp.async 4-stage.
// CTA tile 128(p) x 256(o), BK=32. 8 warps, warp tile 64x64.
// Stage: A@+0 (8KB) + B@+8192 (16KB) = 24KB; 4 stages = 96KB dynamic smem.
// Epilogue: bias + exp + exp-sum -> g_sum; fp16 exp(logit) -> g_logits [b][f][c].
// ===========================================================================
#define STAGE_BYTES 24576
#define B_OFF 8192
#define STAGE_PITCH 264   // halves, staging pitch (256 + 8)

__global__ __launch_bounds__(256) void gemm_mma(
    const float* __restrict__ bias)
{
    extern __shared__ __align__(128) uint8_t smdyn[];
    __shared__ float sm_red[8];
    __shared__ float sm_bias[256];

    const int b   = blockIdx.z;
    const int p0  = blockIdx.x * 128;
    const int o0  = blockIdx.y * 256;
    const int tid = threadIdx.x;
    const int wid = tid >> 5;
    const int lane = tid & 31;
    const int wm = (wid & 1) * 64;       // warp p base
    const int wn = (wid >> 1) * 64;      // warp o base

    sm_bias[tid] = bias[o0 + tid];

    const uint32_t smb = smem_u32(smdyn);

    // cp.async mapping. A: 512 chunks (128 rows x 4), 2 per thread.
    const int rowA = tid >> 1;
    const int chA  = (tid & 1) * 2;
    const __half* aSrc = g_xh + (size_t)b * ELEMS + (size_t)(p0 + rowA) * C + chA * 8;
    const uint32_t aDst0 = swz(rowA, chA), aDst1 = swz(rowA, chA + 1);
    // B: 1024 chunks (256 rows x 4), 4 per thread (one row, 64B contiguous).
    const int rowB = tid;
    const __half* bSrc = g_Wh + (size_t)(o0 + rowB) * C;
    const uint32_t bDst0 = B_OFF + swz(rowB, 0), bDst1 = B_OFF + swz(rowB, 1);
    const uint32_t bDst2 = B_OFF + swz(rowB, 2), bDst3 = B_OFF + swz(rowB, 3);

    // ldmatrix addresses (stage-relative)
    uint32_t aLd[2][4], bLd[2][4];
    #pragma unroll
    for (int ks = 0; ks < 2; ks++) {
        #pragma unroll
        for (int mi = 0; mi < 4; mi++) {
            const int row = wm + mi * 16 + (lane & 15);
            aLd[ks][mi] = smb + swz(row, ks * 2 + (lane >> 4));
        }
        #pragma unroll
        for (int np = 0; np < 4; np++) {
            const int g = lane >> 3;
            const int row = wn + np * 16 + ((g >> 1) << 3) + (lane & 7);
            bLd[ks][np] = smb + B_OFF + swz(row, ks * 2 + (g & 1));
        }
    }

    float acc[4][8][4];
    #pragma unroll
    for (int mi = 0; mi < 4; mi++)
        #pragma unroll
        for (int ni = 0; ni < 8; ni++)
            #pragma unroll
            for (int r = 0; r < 4; r++) acc[mi][ni][r] = 0.f;

    // prefetch stages 0..2
    #pragma unroll
    for (int kt = 0; kt < 3; kt++) {
        const uint32_t sb = smb + kt * STAGE_BYTES;
        const __half* as = aSrc + kt * 32;
        const __half* bs = bSrc + kt * 32;
        cp16(sb + aDst0, as);      cp16(sb + aDst1, as + 8);
        cp16(sb + bDst0, bs);      cp16(sb + bDst1, bs + 8);
        cp16(sb + bDst2, bs + 16); cp16(sb + bDst3, bs + 24);
        CP_COMMIT();
    }

    for (int kt = 0; kt < 16; kt++) {
        CP_WAIT2();
        __syncthreads();
        if (kt + 3 < 16) {
            const uint32_t sb = smb + ((kt + 3) & 3) * STAGE_BYTES;
            const __half* as = aSrc + (kt + 3) * 32;
            const __half* bs = bSrc + (kt + 3) * 32;
            cp16(sb + aDst0, as);      cp16(sb + aDst1, as + 8);
            cp16(sb + bDst0, bs);      cp16(sb + bDst1, bs + 8);
            cp16(sb + bDst2, bs + 16); cp16(sb + bDst3, bs + 24);
        }
        CP_COMMIT();

        const uint32_t stA = (kt & 3) * STAGE_BYTES;
        #pragma unroll
        for (int ks = 0; ks < 2; ks++) {
            uint32_t ar[4][4], br[4][4];
            #pragma unroll
            for (int mi = 0; mi < 4; mi++) ldsm4(ar[mi], aLd[ks][mi] + stA);
            #pragma unroll
            for (int np = 0; np < 4; np++) ldsm4(br[np], bLd[ks][np] + stA);
            #pragma unroll
            for (int mi = 0; mi < 4; mi++)
                #pragma unroll
                for (int ni = 0; ni < 8; ni++)
                    mma16816(acc[mi][ni], ar[mi],
                             br[ni >> 1][(ni & 1) * 2], br[ni >> 1][(ni & 1) * 2 + 1]);
        }
    }
    __syncthreads();   // all MMA reads done -> smem reusable as staging

    // ---- epilogue: bias + exp + exp-sum + fp16 exp staging ----
    __half* stg = (__half*)smdyn;
    float esum = 0.f;
    #pragma unroll
    for (int mi = 0; mi < 4; mi++) {
        const int r0 = wm + mi * 16 + (lane >> 2);
        #pragma unroll
        for (int ni = 0; ni < 8; ni++) {
            const int cc = wn + ni * 8 + 2 * (lane & 3);
            const float bv0 = sm_bias[cc], bv1 = sm_bias[cc + 1];
            const float e0 = __expf(acc[mi][ni][0] + bv0);
            const float e1 = __expf(acc[mi][ni][1] + bv1);
            const float e2 = __expf(acc[mi][ni][2] + bv0);
            const float e3 = __expf(acc[mi][ni][3] + bv1);
            esum += e0 + e1 + e2 + e3;
            *(__half2*)(stg + (size_t)r0 * STAGE_PITCH + cc) = __floats2half2_rn(e0, e1);
            *(__half2*)(stg + (size_t)(r0 + 8) * STAGE_PITCH + cc) = __floats2half2_rn(e2, e3);
        }
    }
    #pragma unroll
    for (int o = 16; o > 0; o >>= 1) esum += __shfl_xor_sync(0xffffffffu, esum, o);
    if (lane == 0) sm_red[wid] = esum;
    __syncthreads();
    if (tid == 0) {
        float s = 0.f;
        #pragma unroll
        for (int i = 0; i < 8; i++) s += sm_red[i];
        atomicAdd(&g_sum[b], s);
    }

    // coalesced fp16 store: g_logits[b][f=p0+row][c=o0+seg*8 .. +7]
    __half* dst = g_logits + (size_t)b * ELEMS;
    #pragma unroll
    for (int k = 0; k < 16; k++) {
        const int idx = tid + k * 256;
        const int row = idx >> 5;
        const int seg = idx & 31;
        *(uint4*)(dst + (size_t)(p0 + row) * C + o0 + seg * 8) =
            *(const uint4*)(stg + (size_t)row * STAGE_PITCH + seg * 8);
    }
}

// ===========================================================================
// launch 5: prototypes — column sums of (xh .* expL), fp16 [f][c] layout.
// grid (25 samples, 8 f-groups of 32), 256 threads; thread = channel pair.
// ===========================================================================
__global__ __launch_bounds__(256) void proto_kernel()
{
    const int samp = blockIdx.x;              // 0..24
    const int way  = samp / SHOT;
    const int b    = way * 20 + (samp % SHOT);
    const int tid  = threadIdx.x;             // channel pair index (c = 2*tid)

    const float inv = 1.0f / g_sum[b];
    const __half2* xh = (const __half2*)(g_xh     + (size_t)b * ELEMS) + tid;
    const __half2* lg = (const __half2*)(g_logits + (size_t)b * ELEMS) + tid;

    float a0 = 0.f, a1 = 0.f;
    const int f0 = blockIdx.y * 32;
    #pragma unroll 8
    for (int f = f0; f < f0 + 32; f++) {
        const float2 xf = __half22float2(xh[(size_t)f * 256]);
        const float2 lf = __half22float2(lg[(size_t)f * 256]);
        a0 += xf.x * lf.x;
        a1 += xf.y * lf.y;
    }
    atomicAdd(&g_protoAcc[way * C + 2 * tid],     a0 * inv);
    atomicAdd(&g_protoAcc[way * C + 2 * tid + 1], a1 * inv);
}

// ===========================================================================
// launch 6: score partials. grid (4 chunks, 75 queries); thread = pixel f.
// ===========================================================================
__global__ __launch_bounds__(256) void score_partial_kernel()
{
    const int chunk = blockIdx.x;
    const int n     = blockIdx.y;
    const int way   = n / 15;
    const int b     = way * 20 + SHOT + (n % 15);
    const int tid   = threadIdx.x;
    const int c0    = chunk * CPERCHUNK;

    __shared__ float s_sm[WAY][CPERCHUNK];
    for (int i = tid; i < WAY * CPERCHUNK; i += 256)
        s_sm[i / CPERCHUNK][i % CPERCHUNK] =
            g_protoAcc[(i / CPERCHUNK) * C + c0 + (i % CPERCHUNK)];
    __syncthreads();

    const float inv = 1.0f / g_sum[b];
    const __half* lg = g_logits + (size_t)b * ELEMS + (size_t)tid * C + c0;
    const __half* xh = g_xh     + (size_t)b * ELEMS + (size_t)tid * C + c0;

    float qq = 0.f, d0 = 0.f, d1 = 0.f, d2 = 0.f, d3 = 0.f, d4 = 0.f;
    for (int c8 = 0; c8 < CPERCHUNK / 8; c8++) {
        const uint4 ul = *(const uint4*)(lg + c8 * 8);
        const uint4 ux = *(const uint4*)(xh + c8 * 8);
        #pragma unroll
        for (int t = 0; t < 4; t++) {
            const float2 lf = __half22float2(((const __half2*)&ul)[t]);
            const float2 xf = __half22float2(((const __half2*)&ux)[t]);
            const int c = c8 * 8 + t * 2;
            const float q0 = xf.x * lf.x * inv;
            const float q1 = xf.y * lf.y * inv;
            qq += q0 * q0 + q1 * q1;
            d0 += q0 * s_sm[0][c] + q1 * s_sm[0][c + 1];
            d1 += q0 * s_sm[1][c] + q1 * s_sm[1][c + 1];
            d2 += q0 * s_sm[2][c] + q1 * s_sm[2][c + 1];
            d3 += q0 * s_sm[3][c] + q1 * s_sm[3][c + 1];
            d4 += q0 * s_sm[4][c] + q1 * s_sm[4][c + 1];
        }
    }
    float* pp = g_part + (((size_t)n * NCHUNK + chunk) * P + tid) * 8;
    *(float4*)(pp)     = make_float4(qq, d0, d1, d2);
    *(float4*)(pp + 4) = make_float4(d3, d4, 0.f, 0.f);
}

// ===========================================================================
// launch 7: final. 75 blocks; thread = pixel. Cosine, softmax, spatial mean.
// ===========================================================================
__global__ __launch_bounds__(256) void final_kernel(float* __restrict__ out)
{
    const int n   = blockIdx.x;
    const int tid = threadIdx.x;

    __shared__ float sn_sm[WAY];
    __shared__ float accum[WAY];
    if (tid < WAY) accum[tid] = 0.f;

    if (tid < WAY * 32) {
        const int m = tid >> 5, lane = tid & 31;
        float v = 0.f;
        #pragma unroll
        for (int i = 0; i < C / 32; i++) {
            const float t = g_protoAcc[m * C + lane + i * 32];
            v += t * t;
        }
        #pragma unroll
        for (int o = 16; o > 0; o >>= 1) v += __shfl_xor_sync(0xffffffffu, v, o);
        if (lane == 0) sn_sm[m] = fmaxf(sqrtf(v), 1e-8f);
    }
    __syncthreads();

    float qq = 0.f, d[WAY] = {0.f, 0.f, 0.f, 0.f, 0.f};
    #pragma unroll
    for (int ch = 0; ch < NCHUNK; ch++) {
        const float* pp = g_part + (((size_t)n * NCHUNK + ch) * P + tid) * 8;
        const float4 v0 = *(const float4*)(pp);
        const float4 v1 = *(const float4*)(pp + 4);
        qq += v0.x; d[0] += v0.y; d[1] += v0.z; d[2] += v0.w;
        d[3] += v1.x; d[4] += v1.y;
    }
    const float qn = fmaxf(sqrtf(qq), 1e-8f);

    float sc[WAY], m5 = -1e30f;
    #pragma unroll
    for (int m = 0; m < WAY; m++) {
        sc[m] = 10.0f * d[m] / (qn * sn_sm[m]);
        m5 = fmaxf(m5, sc[m]);
    }
    float se = 0.f;
    #pragma unroll
    for (int m = 0; m < WAY; m++) { sc[m] = __expf(sc[m] - m5); se += sc[m]; }
    const float inv = 1.0f / (se * (float)P);
    #pragma unroll
    for (int m = 0; m < WAY; m++) atomicAdd(&accum[m], sc[m] * inv);
    __syncthreads();
    if (tid < WAY) out[n * WAY + tid] = accum[tid];
}

// ===========================================================================
extern "C" void kernel_launch(void* const* d_in, const int* in_sizes, int n_in,
                              void* d_out, int out_size)
{
    const float* x    = (const float*)d_in[0];
    const float* W    = (const float*)d_in[1];
    const float* bias = (const float*)d_in[2];
    float* out = (float*)d_out;

    cudaFuncSetAttribute(gemm_mma, cudaFuncAttributeMaxDynamicSharedMemorySize, 98304);

    zero_kernel<<<1, 256>>>();                          // launch 1
    pad_kernel<<<1, 32>>>();                            // launch 2
    conv_kernel<<<dim3(4, NSAMP + 1), 256>>>(x, W);     // launch 3
    gemm_mma<<<dim3(2, 2, NSAMP), 256, 98304>>>(bias);  // launch 4 <- ncu capture slot
    proto_kernel<<<dim3(25, 8), 256>>>();               // launch 5
    score_partial_kernel<<<dim3(NCHUNK, NQ), 256>>>();  // launch 6
    final_kernel<<<NQ, 256>>>(out);                     // launch 7
}

// round 16
// speedup vs baseline: 1.2203x; 1.2203x over previous
#include <cuda_runtime.h>
#include <cuda_fp16.h>
#include <math.h>
#include <stdint.h>

// x: (100, 512, 16, 16) fp32 ; W: (512,512) (outC,inC) ; b: (512,) ; out: (75,5)
#define NSAMP 100
#define C 512
#define P 256
#define ELEMS (C*P)
#define WAY 5
#define SHOT 5
#define NQ 75
#define NCHUNK 4
#define CPERCHUNK 128

__device__ __half g_xh[NSAMP * ELEMS];         // x^T fp16 [b][f][c], 26 MB
__device__ __half g_Wh[C * C];                 // W fp16 [o][c]
__device__ __half g_logits[NSAMP * ELEMS];     // [b][f][c] fp16: exp(logit+bias), 26 MB
__device__ float  g_sum[NSAMP];
__device__ float  g_protoAcc[WAY * C];
__device__ float  g_part[NQ * NCHUNK * P * 8];

// ===========================================================================
__device__ __forceinline__ uint32_t smem_u32(const void* p) {
    uint32_t a;
    asm("{ .reg .u64 t; cvta.to.shared.u64 t, %1; cvt.u32.u64 %0, t; }"
        : "=r"(a) : "l"(p));
    return a;
}
__device__ __forceinline__ void ldsm4(uint32_t (&r)[4], uint32_t addr) {
    asm volatile("ldmatrix.sync.aligned.m8n8.x4.shared.b16 {%0,%1,%2,%3}, [%4];"
                 : "=r"(r[0]), "=r"(r[1]), "=r"(r[2]), "=r"(r[3]) : "r"(addr));
}
__device__ __forceinline__ void mma16816(float (&d)[4], const uint32_t (&a)[4],
                                         uint32_t b0, uint32_t b1) {
    asm volatile(
        "mma.sync.aligned.m16n8k16.row.col.f32.f16.f16.f32 "
        "{%0,%1,%2,%3},{%4,%5,%6,%7},{%8,%9},{%0,%1,%2,%3};"
        : "+f"(d[0]), "+f"(d[1]), "+f"(d[2]), "+f"(d[3])
        : "r"(a[0]), "r"(a[1]), "r"(a[2]), "r"(a[3]), "r"(b0), "r"(b1));
}
__device__ __forceinline__ uint32_t pkh(float a, float b) {
    __half2 h = __floats2half2_rn(a, b);
    return *(uint32_t*)&h;
}
// 16B-chunk XOR swizzle inside a 64B row (4 chunks)
__device__ __forceinline__ int swz(int row, int ch) {
    return row * 64 + ((ch ^ ((row >> 1) & 3)) << 4);
}
__device__ __forceinline__ void cp16(uint32_t dst, const void* src) {
    asm volatile("cp.async.cg.shared.global [%0], [%1], 16;"
                 :: "r"(dst), "l"(src));
}
#define CP_COMMIT() asm volatile("cp.async.commit_group;" ::: "memory")
#define CP_WAIT2()  asm volatile("cp.async.wait_group 2;" ::: "memory")

// ===========================================================================
// launch 1: convert. b<100: xT fp16 [b][f][c] (8 c-groups of 64 per sample);
// b==100: W fp16 + zero accumulators (block 0).
// grid (8, 101), 256 threads.
// ===========================================================================
__global__ __launch_bounds__(256) void conv_kernel(
    const float* __restrict__ x, const float* __restrict__ W)
{
    const int b = blockIdx.y;
    const int f = threadIdx.x;
    if (b < NSAMP) {
        const int c0 = blockIdx.x * 64;
        const float* xb = x + (size_t)b * ELEMS + f;
        __half* dst = g_xh + (size_t)b * ELEMS + (size_t)f * C + c0;
        #pragma unroll
        for (int k = 0; k < 8; k++) {
            const float* sp = xb + (size_t)(c0 + k * 8) * P;
            uint4 u;
            u.x = pkh(sp[0], sp[P]);
            u.y = pkh(sp[2 * P], sp[3 * P]);
            u.z = pkh(sp[4 * P], sp[5 * P]);
            u.w = pkh(sp[6 * P], sp[7 * P]);
            *(uint4*)(dst + k * 8) = u;
        }
    } else {
        const int start = blockIdx.x * 32768;
        #pragma unroll 4
        for (int t = 0; t < 32; t++) {
            const int i4 = start + (t * 256 + threadIdx.x) * 4;
            const float4 v = *(const float4*)(W + i4);
            *(uint2*)(g_Wh + i4) = make_uint2(pkh(v.x, v.y), pkh(v.z, v.w));
        }
        if (blockIdx.x == 0) {
            for (int i = threadIdx.x; i < NSAMP + WAY * C; i += 256) {
                if (i < NSAMP) g_sum[i] = 0.f;
                else g_protoAcc[i - NSAMP] = 0.f;
            }
        }
    }
}

// ===========================================================================
// launch 2: fp16 mma.sync GEMM, cp.async 4-stage (R14 measured 51us config).
// CTA 128(p) x 128(o), BK=32, 8 warps, warp 64x32; 64KB smem, 2 CTA/SM.
// Epilogue: bias + exp + exp-sum -> g_sum; fp16 exp(logit) -> g_logits [b][f][c].
// ===========================================================================
#define STAGE_PITCH 136   // halves, staging pitch

__global__ __launch_bounds__(256, 2) void gemm_mma(
    const float* __restrict__ bias)
{
    extern __shared__ __align__(128) uint8_t smdyn[];
    __shared__ float sm_red[8];
    __shared__ float sm_bias[128];

    const int b   = blockIdx.z;
    const int p0  = blockIdx.x * 128;
    const int o0  = blockIdx.y * 128;
    const int tid = threadIdx.x;
    const int wid = tid >> 5;
    const int lane = tid & 31;
    const int wm = (wid & 1) * 64;
    const int wn = (wid >> 1) * 32;

    if (tid < 128) sm_bias[tid] = bias[o0 + tid];

    const uint32_t smb = smem_u32(smdyn);

    // cp.async mapping: thread -> (row = tid>>1, 2 chunks of 16B)
    const int rowcp = tid >> 1;
    const int chcp  = (tid & 1) * 2;
    const __half* aSrc = g_xh + (size_t)b * ELEMS + (size_t)(p0 + rowcp) * C + chcp * 8;
    const __half* bSrc = g_Wh + (size_t)(o0 + rowcp) * C + chcp * 8;
    const uint32_t aDst0 = swz(rowcp, chcp),     aDst1 = swz(rowcp, chcp + 1);
    const uint32_t bDst0 = 8192 + aDst0,         bDst1 = 8192 + aDst1;

    // ldmatrix addresses (stage-relative)
    uint32_t aLd[2][4], bLd[2][2];
    #pragma unroll
    for (int ks = 0; ks < 2; ks++) {
        #pragma unroll
        for (int mi = 0; mi < 4; mi++) {
            const int row = wm + mi * 16 + (lane & 15);
            aLd[ks][mi] = smb + swz(row, ks * 2 + (lane >> 4));
        }
        #pragma unroll
        for (int np = 0; np < 2; np++) {
            const int g = lane >> 3;
            const int row = wn + np * 16 + ((g >> 1) << 3) + (lane & 7);
            bLd[ks][np] = smb + 8192 + swz(row, ks * 2 + (g & 1));
        }
    }

    float acc[4][4][4];
    #pragma unroll
    for (int mi = 0; mi < 4; mi++)
        #pragma unroll
        for (int ni = 0; ni < 4; ni++)
            #pragma unroll
            for (int r = 0; r < 4; r++) acc[mi][ni][r] = 0.f;

    // prefetch stages 0..2
    #pragma unroll
    for (int kt = 0; kt < 3; kt++) {
        const uint32_t sb = smb + kt * 16384;
        const __half* as = aSrc + kt * 32;
        const __half* bs = bSrc + kt * 32;
        cp16(sb + aDst0, as); cp16(sb + aDst1, as + 8);
        cp16(sb + bDst0, bs); cp16(sb + bDst1, bs + 8);
        CP_COMMIT();
    }

    for (int kt = 0; kt < 16; kt++) {
        CP_WAIT2();
        __syncthreads();
        if (kt + 3 < 16) {
            const uint32_t sb = smb + ((kt + 3) & 3) * 16384;
            const __half* as = aSrc + (kt + 3) * 32;
            const __half* bs = bSrc + (kt + 3) * 32;
            cp16(sb + aDst0, as); cp16(sb + aDst1, as + 8);
            cp16(sb + bDst0, bs); cp16(sb + bDst1, bs + 8);
        }
        CP_COMMIT();

        const uint32_t stA = (kt & 3) * 16384;
        #pragma unroll
        for (int ks = 0; ks < 2; ks++) {
            uint32_t ar[4][4], br[2][4];
            #pragma unroll
            for (int mi = 0; mi < 4; mi++) ldsm4(ar[mi], aLd[ks][mi] + stA);
            #pragma unroll
            for (int np = 0; np < 2; np++) ldsm4(br[np], bLd[ks][np] + stA);
            #pragma unroll
            for (int mi = 0; mi < 4; mi++)
                #pragma unroll
                for (int ni = 0; ni < 4; ni++)
                    mma16816(acc[mi][ni], ar[mi],
                             br[ni >> 1][(ni & 1) * 2], br[ni >> 1][(ni & 1) * 2 + 1]);
        }
    }
    __syncthreads();   // all MMA reads done -> smem reusable as staging

    // ---- epilogue: bias + exp + exp-sum + fp16 exp staging ----
    __half* stg = (__half*)smdyn;
    float esum = 0.f;
    #pragma unroll
    for (int mi = 0; mi < 4; mi++) {
        const int r0 = wm + mi * 16 + (lane >> 2);
        #pragma unroll
        for (int ni = 0; ni < 4; ni++) {
            const int cc = wn + ni * 8 + 2 * (lane & 3);
            const float bv0 = sm_bias[cc], bv1 = sm_bias[cc + 1];
            const float e0 = __expf(acc[mi][ni][0] + bv0);
            const float e1 = __expf(acc[mi][ni][1] + bv1);
            const float e2 = __expf(acc[mi][ni][2] + bv0);
            const float e3 = __expf(acc[mi][ni][3] + bv1);
            esum += e0 + e1 + e2 + e3;
            *(__half2*)(stg + (size_t)r0 * STAGE_PITCH + cc) = __floats2half2_rn(e0, e1);
            *(__half2*)(stg + (size_t)(r0 + 8) * STAGE_PITCH + cc) = __floats2half2_rn(e2, e3);
        }
    }
    #pragma unroll
    for (int o = 16; o > 0; o >>= 1) esum += __shfl_xor_sync(0xffffffffu, esum, o);
    if (lane == 0) sm_red[wid] = esum;
    __syncthreads();
    if (tid == 0) {
        float s = 0.f;
        #pragma unroll
        for (int i = 0; i < 8; i++) s += sm_red[i];
        atomicAdd(&g_sum[b], s);
    }

    // coalesced fp16 store: g_logits[b][f=p0+row][c=o0+seg*8 .. +7]
    __half* dst = g_logits + (size_t)b * ELEMS;
    #pragma unroll
    for (int k = 0; k < 8; k++) {
        const int idx = tid + k * 256;
        const int row = idx >> 4;
        const int seg = idx & 15;
        *(uint4*)(dst + (size_t)(p0 + row) * C + o0 + seg * 8) =
            *(const uint4*)(stg + (size_t)row * STAGE_PITCH + seg * 8);
    }
}

// ===========================================================================
// launch 3: prototypes — column sums of (xh .* expL), fp16 [f][c] layout.
// grid (25 samples, 8 f-groups of 32), 256 threads; thread = channel pair.
// ===========================================================================
__global__ __launch_bounds__(256) void proto_kernel()
{
    const int samp = blockIdx.x;              // 0..24
    const int way  = samp / SHOT;
    const int b    = way * 20 + (samp % SHOT);
    const int tid  = threadIdx.x;             // channel pair index (c = 2*tid)

    const float inv = 1.0f / g_sum[b];
    const __half2* xh = (const __half2*)(g_xh     + (size_t)b * ELEMS) + tid;
    const __half2* lg = (const __half2*)(g_logits + (size_t)b * ELEMS) + tid;

    float a0 = 0.f, a1 = 0.f;
    const int f0 = blockIdx.y * 32;
    #pragma unroll 8
    for (int f = f0; f < f0 + 32; f++) {
        const float2 xf = __half22float2(xh[(size_t)f * 256]);
        const float2 lf = __half22float2(lg[(size_t)f * 256]);
        a0 += xf.x * lf.x;
        a1 += xf.y * lf.y;
    }
    atomicAdd(&g_protoAcc[way * C + 2 * tid],     a0 * inv);
    atomicAdd(&g_protoAcc[way * C + 2 * tid + 1], a1 * inv);
}

// ===========================================================================
// launch 4 (ncu capture slot): score partials. grid (4 chunks, 75 queries).
// ===========================================================================
__global__ __launch_bounds__(256) void score_partial_kernel()
{
    const int chunk = blockIdx.x;
    const int n     = blockIdx.y;
    const int way   = n / 15;
    const int b     = way * 20 + SHOT + (n % 15);
    const int tid   = threadIdx.x;
    const int c0    = chunk * CPERCHUNK;

    __shared__ float s_sm[WAY][CPERCHUNK];
    for (int i = tid; i < WAY * CPERCHUNK; i += 256)
        s_sm[i / CPERCHUNK][i % CPERCHUNK] =
            g_protoAcc[(i / CPERCHUNK) * C + c0 + (i % CPERCHUNK)];
    __syncthreads();

    const float inv = 1.0f / g_sum[b];
    const __half* lg = g_logits + (size_t)b * ELEMS + (size_t)tid * C + c0;
    const __half* xh = g_xh     + (size_t)b * ELEMS + (size_t)tid * C + c0;

    float qq = 0.f, d0 = 0.f, d1 = 0.f, d2 = 0.f, d3 = 0.f, d4 = 0.f;
    for (int c8 = 0; c8 < CPERCHUNK / 8; c8++) {
        const uint4 ul = *(const uint4*)(lg + c8 * 8);
        const uint4 ux = *(const uint4*)(xh + c8 * 8);
        #pragma unroll
        for (int t = 0; t < 4; t++) {
            const float2 lf = __half22float2(((const __half2*)&ul)[t]);
            const float2 xf = __half22float2(((const __half2*)&ux)[t]);
            const int c = c8 * 8 + t * 2;
            const float q0 = xf.x * lf.x * inv;
            const float q1 = xf.y * lf.y * inv;
            qq += q0 * q0 + q1 * q1;
            d0 += q0 * s_sm[0][c] + q1 * s_sm[0][c + 1];
            d1 += q0 * s_sm[1][c] + q1 * s_sm[1][c + 1];
            d2 += q0 * s_sm[2][c] + q1 * s_sm[2][c + 1];
            d3 += q0 * s_sm[3][c] + q1 * s_sm[3][c + 1];
            d4 += q0 * s_sm[4][c] + q1 * s_sm[4][c + 1];
        }
    }
    float* pp = g_part + (((size_t)n * NCHUNK + chunk) * P + tid) * 8;
    *(float4*)(pp)     = make_float4(qq, d0, d1, d2);
    *(float4*)(pp + 4) = make_float4(d3, d4, 0.f, 0.f);
}

// ===========================================================================
// launch 5: final. 75 blocks; thread = pixel. Cosine, softmax, spatial mean.
// ===========================================================================
__global__ __launch_bounds__(256) void final_kernel(float* __restrict__ out)
{
    const int n   = blockIdx.x;
    const int tid = threadIdx.x;

    __shared__ float sn_sm[WAY];
    __shared__ float accum[WAY];
    if (tid < WAY) accum[tid] = 0.f;

    if (tid < WAY * 32) {
        const int m = tid >> 5, lane = tid & 31;
        float v = 0.f;
        #pragma unroll
        for (int i = 0; i < C / 32; i++) {
            const float t = g_protoAcc[m * C + lane + i * 32];
            v += t * t;
        }
        #pragma unroll
        for (int o = 16; o > 0; o >>= 1) v += __shfl_xor_sync(0xffffffffu, v, o);
        if (lane == 0) sn_sm[m] = fmaxf(sqrtf(v), 1e-8f);
    }
    __syncthreads();

    float qq = 0.f, d[WAY] = {0.f, 0.f, 0.f, 0.f, 0.f};
    #pragma unroll
    for (int ch = 0; ch < NCHUNK; ch++) {
        const float* pp = g_part + (((size_t)n * NCHUNK + ch) * P + tid) * 8;
        const float4 v0 = *(const float4*)(pp);
        const float4 v1 = *(const float4*)(pp + 4);
        qq += v0.x; d[0] += v0.y; d[1] += v0.z; d[2] += v0.w;
        d[3] += v1.x; d[4] += v1.y;
    }
    const float qn = fmaxf(sqrtf(qq), 1e-8f);

    float sc[WAY], m5 = -1e30f;
    #pragma unroll
    for (int m = 0; m < WAY; m++) {
        sc[m] = 10.0f * d[m] / (qn * sn_sm[m]);
        m5 = fmaxf(m5, sc[m]);
    }
    float se = 0.f;
    #pragma unroll
    for (int m = 0; m < WAY; m++) { sc[m] = __expf(sc[m] - m5); se += sc[m]; }
    const float inv = 1.0f / (se * (float)P);
    #pragma unroll
    for (int m = 0; m < WAY; m++) atomicAdd(&accum[m], sc[m] * inv);
    __syncthreads();
    if (tid < WAY) out[n * WAY + tid] = accum[tid];
}

// ===========================================================================
extern "C" void kernel_launch(void* const* d_in, const int* in_sizes, int n_in,
                              void* d_out, int out_size)
{
    const float* x    = (const float*)d_in[0];
    const float* W    = (const float*)d_in[1];
    const float* bias = (const float*)d_in[2];
    float* out = (float*)d_out;

    cudaFuncSetAttribute(gemm_mma, cudaFuncAttributeMaxDynamicSharedMemorySize, 65536);

    conv_kernel<<<dim3(8, NSAMP + 1), 256>>>(x, W);     // launch 1
    gemm_mma<<<dim3(2, 4, NSAMP), 256, 65536>>>(bias);  // launch 2
    proto_kernel<<<dim3(25, 8), 256>>>();               // launch 3
    score_partial_kernel<<<dim3(NCHUNK, NQ), 256>>>();  // launch 4 <- ncu capture slot
    final_kernel<<<NQ, 256>>>(out);                     // launch 5
}